// round 13
// baseline (speedup 1.0000x reference)
#include <cuda_runtime.h>
#include <math.h>

#define NB  16
#define C   256
#define H   80
#define W   80
#define MIP 8
#define L   160            // H + W
#define BN_EPS 1e-5f

#define NSTAGES   4
#define NB_STAGE  (NB / NSTAGES)           // 4 batches per stage
#define PLANES_ST (NB_STAGE * C)           // 1024 planes per stage (26.2 MB)

// Scratch (device globals: no allocations allowed)
__device__ float g_y [NB * C * L];   // [n][c][l]: l<80 row means (x_h), l>=80 col means (x_w)
__device__ float g_ah[NB * C * H];
__device__ float g_aw[NB * C * W];

__device__ __forceinline__ float fsig(float v) { return 1.f / (1.f + __expf(-v)); }

// ---------------------------------------------------------------------------
// k1 (R7-proven): one block (320 thr) per plane. 20 col-groups x 16 row-groups;
// column partials in registers, small partials through padded smem.
// ---------------------------------------------------------------------------
__global__ __launch_bounds__(320) void k1_means(const float* __restrict__ x, int plane0) {
    __shared__ float s_row[H][21];     // 21: gcd(21,32)=1
    __shared__ float s_col[W][17];     // 17: gcd(17,32)=1
    const int plane = plane0 + blockIdx.x;
    const int t  = threadIdx.x;
    const int q  = t % 20;             // float4 column group
    const int rg = t / 20;             // row group 0..15
    const float4* __restrict__ xp = (const float4*)(x + (size_t)plane * (H * W));

    float4 cacc = make_float4(0.f, 0.f, 0.f, 0.f);
    #pragma unroll
    for (int i = 0; i < 5; i++) {
        int r = i * 16 + rg;
        float4 v = xp[r * 20 + q];
        cacc.x += v.x; cacc.y += v.y; cacc.z += v.z; cacc.w += v.w;
        s_row[r][q] = v.x + v.y + v.z + v.w;
    }
    s_col[4 * q + 0][rg] = cacc.x;
    s_col[4 * q + 1][rg] = cacc.y;
    s_col[4 * q + 2][rg] = cacc.z;
    s_col[4 * q + 3][rg] = cacc.w;
    __syncthreads();

    const float inv80 = 1.0f / 80.0f;
    if (t < H) {
        float s = 0.f;
        #pragma unroll
        for (int j = 0; j < 20; j++) s += s_row[t][j];
        g_y[(size_t)plane * L + t] = s * inv80;          // x_h (row mean)
    } else if (t >= 160 && t < 160 + W) {
        int col = t - 160;
        float s = 0.f;
        #pragma unroll
        for (int g = 0; g < 16; g++) s += s_col[col][g];
        g_y[(size_t)plane * L + H + col] = s * inv80;    // x_w (col mean)
    }
}

// ---------------------------------------------------------------------------
// k2 (R7-proven): grid (NB_STAGE, 2), block 320.
// GEMM1 split-K (MLP 8) + smem combine + BN + swish; GEMM2 register-hoisted.
// ---------------------------------------------------------------------------
__global__ __launch_bounds__(320) void k2_attn(const float* __restrict__ w_fc,
                                               const float* __restrict__ bn_gamma,
                                               const float* __restrict__ bn_beta,
                                               const float* __restrict__ bn_mean,
                                               const float* __restrict__ bn_var,
                                               const float* __restrict__ w_h,
                                               const float* __restrict__ w_w,
                                               int n0) {
    __shared__ float ys[MIP * L];        // swished bottleneck (5 KB)
    __shared__ float wfcT[C * MIP];      // w_fc transposed (8 KB)
    __shared__ float ps[2 * MIP * L];    // split-K partials (10 KB)
    const int n = n0 + blockIdx.x;
    const int t = threadIdx.x;

    if (t < C) {
        #pragma unroll
        for (int m = 0; m < MIP; m++) wfcT[t * MIP + m] = w_fc[m * C + t];
    }
    __syncthreads();

    const float* __restrict__ yb = g_y + (size_t)n * C * L;
    {
        const int l    = t % L;
        const int half = t / L;                          // 0 or 1
        const int c0   = half * (C / 2);
        float acc[MIP];
        #pragma unroll
        for (int m = 0; m < MIP; m++) acc[m] = 0.f;
        #pragma unroll 8
        for (int c = 0; c < C / 2; c++) {
            float v = yb[(c0 + c) * L + l];              // coalesced across threads
            const float4* wr = (const float4*)(wfcT + (c0 + c) * MIP);
            float4 a = wr[0], b = wr[1];
            acc[0] = fmaf(a.x, v, acc[0]); acc[1] = fmaf(a.y, v, acc[1]);
            acc[2] = fmaf(a.z, v, acc[2]); acc[3] = fmaf(a.w, v, acc[3]);
            acc[4] = fmaf(b.x, v, acc[4]); acc[5] = fmaf(b.y, v, acc[5]);
            acc[6] = fmaf(b.z, v, acc[6]); acc[7] = fmaf(b.w, v, acc[7]);
        }
        #pragma unroll
        for (int m = 0; m < MIP; m++) ps[half * MIP * L + m * L + l] = acc[m];
    }
    __syncthreads();

    if (t < L) {
        #pragma unroll
        for (int m = 0; m < MIP; m++) {
            float s  = ps[m * L + t] + ps[MIP * L + m * L + t];
            float iv = bn_gamma[m] * rsqrtf(bn_var[m] + BN_EPS);
            float vv = s * iv + (bn_beta[m] - bn_mean[m] * iv);
            ys[m * L + t] = vv * fsig(vv);
        }
    }
    __syncthreads();

    const int l  = t % 80;
    const int cg = t / 80;                               // 0..3
    const int c0 = (blockIdx.y * 4 + cg) * 32;
    float yh[MIP], yw[MIP];
    #pragma unroll
    for (int m = 0; m < MIP; m++) { yh[m] = ys[m * L + l]; yw[m] = ys[m * L + H + l]; }

    float* __restrict__ ahp = g_ah + (size_t)n * C * H;
    float* __restrict__ awp = g_aw + (size_t)n * C * W;
    #pragma unroll 4
    for (int c = c0; c < c0 + 32; c++) {
        const float4* wh4 = (const float4*)(w_h + c * MIP);
        const float4* ww4 = (const float4*)(w_w + c * MIP);
        float4 ha = wh4[0], hb = wh4[1];
        float4 wa = ww4[0], wb = ww4[1];
        float sh = 0.f, sw = 0.f;
        sh = fmaf(ha.x, yh[0], sh); sh = fmaf(ha.y, yh[1], sh);
        sh = fmaf(ha.z, yh[2], sh); sh = fmaf(ha.w, yh[3], sh);
        sh = fmaf(hb.x, yh[4], sh); sh = fmaf(hb.y, yh[5], sh);
        sh = fmaf(hb.z, yh[6], sh); sh = fmaf(hb.w, yh[7], sh);
        sw = fmaf(wa.x, yw[0], sw); sw = fmaf(wa.y, yw[1], sw);
        sw = fmaf(wa.z, yw[2], sw); sw = fmaf(wa.w, yw[3], sw);
        sw = fmaf(wb.x, yw[4], sw); sw = fmaf(wb.y, yw[5], sw);
        sw = fmaf(wb.z, yw[6], sw); sw = fmaf(wb.w, yw[7], sw);
        ahp[c * H + l] = fsig(sh);
        awp[c * W + l] = fsig(sw);
    }
}

// ---------------------------------------------------------------------------
// k3: one block (320 thr) per plane — same parallelism per launch as the
// proven R7 k3 (1024 blocks). a-maps staged in smem; 5 front-batched LDG.128
// per thread; streaming stores. Reads the stage chunk just loaded by k1.
// ---------------------------------------------------------------------------
__global__ __launch_bounds__(320) void k3_apply(const float* __restrict__ x,
                                                float* __restrict__ out,
                                                int plane0) {
    __shared__ float  s_ah[H];
    __shared__ float4 s_aw4[20];
    const int plane = plane0 + blockIdx.x;
    const int t  = threadIdx.x;
    const int q  = t % 20;
    const int rg = t / 20;

    if (t < H)               s_ah[t]       = g_ah[(size_t)plane * H + t];
    else if (t < H + 20)     s_aw4[t - H]  = ((const float4*)g_aw)[(size_t)plane * 20 + (t - H)];
    __syncthreads();

    const float4* __restrict__ xp = (const float4*)x + (size_t)plane * 1600;
    float4* __restrict__ op = (float4*)out + (size_t)plane * 1600;

    float4 v[5];
    #pragma unroll
    for (int i = 0; i < 5; i++)                  // front-batched: 5 LDG.128 in flight
        v[i] = xp[(i * 16 + rg) * 20 + q];

    const float4 aw = s_aw4[q];
    #pragma unroll
    for (int i = 0; i < 5; i++) {
        int r = i * 16 + rg;
        float ah = s_ah[r];
        float4 rr;
        rr.x = v[i].x * (ah * aw.x);
        rr.y = v[i].y * (ah * aw.y);
        rr.z = v[i].z * (ah * aw.z);
        rr.w = v[i].w * (ah * aw.w);
        __stcs(op + r * 20 + q, rr);
    }
}

// ---------------------------------------------------------------------------
// Staged pipeline: 4 stages of 4 batches. Per stage the 26 MB x-chunk is read
// by k1, (hopefully) retained in L2 across the tiny k2, and re-read by k3.
// ---------------------------------------------------------------------------
extern "C" void kernel_launch(void* const* d_in, const int* in_sizes, int n_in,
                              void* d_out, int out_size) {
    const float* x        = (const float*)d_in[0];
    const float* w_fc     = (const float*)d_in[1];
    const float* bn_gamma = (const float*)d_in[2];
    const float* bn_beta  = (const float*)d_in[3];
    const float* bn_mean  = (const float*)d_in[4];
    const float* bn_var   = (const float*)d_in[5];
    const float* w_h      = (const float*)d_in[6];
    const float* w_w      = (const float*)d_in[7];
    float* out = (float*)d_out;

    for (int s = 0; s < NSTAGES; s++) {
        const int n0     = s * NB_STAGE;
        const int plane0 = n0 * C;
        k1_means<<<PLANES_ST, 320>>>(x, plane0);
        k2_attn<<<dim3(NB_STAGE, 2), 320>>>(w_fc, bn_gamma, bn_beta, bn_mean,
                                            bn_var, w_h, w_w, n0);
        k3_apply<<<PLANES_ST, 320>>>(x, out, plane0);
    }
}

// round 14
// speedup vs baseline: 1.1663x; 1.1663x over previous
#include <cuda_runtime.h>
#include <math.h>

#define NB   16
#define C    256
#define H    80
#define W    80
#define MIP  8
#define L    160
#define BN_EPS 1e-5f

#define GRID 256
#define TPB  320

// Cross-block state
__device__ float g_y  [NB * C * L];     // raw means per (batch, channel)
__device__ float g_ysw[NB * MIP * L];   // swished bottleneck per batch
__device__ int   g_cnt[NB];             // blocks that wrote means for batch
__device__ int   g_rdy[NB];             // gemm slices done for batch (16 = ready)

__device__ __forceinline__ float fsig(float v) { return 1.f / (1.f + __expf(-v)); }

__device__ __forceinline__ float ldcg(const float* p) {
    float v; asm volatile("ld.global.cg.f32 %0, [%1];" : "=f"(v) : "l"(p)); return v;
}
__device__ __forceinline__ int ld_acq(const int* p) {
    int v; asm volatile("ld.global.acquire.gpu.s32 %0, [%1];" : "=r"(v) : "l"(p)); return v;
}
// Pinned-issue-order 16B load (forces emission BEFORE the following consume phase)
__device__ __forceinline__ float4 ldg_nc4(const float* p) {
    float4 v;
    asm volatile("ld.global.nc.v4.f32 {%0,%1,%2,%3}, [%4];"
                 : "=f"(v.x), "=f"(v.y), "=f"(v.z), "=f"(v.w) : "l"(p));
    return v;
}

// SMEM floats: bufs 3*6400=19200 | s_wfc 2048 | s_row 1680 | s_col 1360
//              s_ys 1280 | s_ah 80 | s_aw 80 | s_bn 16   => 25744 fl = 103.0 KB
#define SM_FLOATS (19200 + 2048 + 1680 + 1360 + 1280 + 80 + 80 + 16)

__global__ void init_state() {
    int i = threadIdx.x;
    if (i < NB) { g_cnt[i] = 0; g_rdy[i] = 0; }
}

__global__ __launch_bounds__(TPB, 2) void fused(const float* __restrict__ x,
                                                const float* __restrict__ w_fc,
                                                const float* __restrict__ bn_gamma,
                                                const float* __restrict__ bn_beta,
                                                const float* __restrict__ bn_mean,
                                                const float* __restrict__ bn_var,
                                                const float* __restrict__ w_h,
                                                const float* __restrict__ w_w,
                                                float* __restrict__ out) {
    extern __shared__ float sm[];
    float4* bufs  = (float4*)sm;                 // 3 x 1600 float4
    float*  s_wfc = sm + 19200;                  // [8][256]
    float*  s_row = s_wfc + 2048;                // [80][21]
    float*  s_col = s_row + 1680;                // [80][17]
    float*  s_ys  = s_col + 1360;                // [1280]
    float*  s_ah  = s_ys + 1280;                 // [80]
    float*  s_aw  = s_ah + 80;                   // [80] (16B aligned)
    float*  s_bn  = s_aw + 80;                   // [16]

    const int b  = blockIdx.x;                   // channel c = b
    const int t  = threadIdx.x;
    const int q  = t % 20;
    const int rg = t / 20;

    for (int i = t; i < MIP * C; i += TPB) s_wfc[i] = w_fc[i];
    if (t < MIP) {
        float iv = bn_gamma[t] * rsqrtf(bn_var[t] + BN_EPS);
        s_bn[t]       = iv;
        s_bn[MIP + t] = bn_beta[t] - bn_mean[t] * iv;
    }
    float wh[MIP], ww[MIP];
    #pragma unroll
    for (int m = 0; m < MIP; m++) {
        wh[m] = w_h[b * MIP + m];
        ww[m] = w_w[b * MIP + m];
    }
    __syncthreads();

    const float inv80 = 1.0f / 80.0f;
    float4* __restrict__ o4 = (float4*)out;

    // ---- consume batch j: attention for channel b + apply from buffered plane ----
    auto do_C = [&](int j) {
        if (t == 0) { while (ld_acq(&g_rdy[j]) != 16) __nanosleep(64); }
        __syncthreads();
        const float* __restrict__ ysg = g_ysw + j * (MIP * L);
        #pragma unroll
        for (int u = 0; u < 4; u++) {
            int idx = t + u * TPB;
            s_ys[idx] = ldcg(ysg + idx);
        }
        __syncthreads();
        if (t < H) {
            float d = 0.f;
            #pragma unroll
            for (int m = 0; m < MIP; m++) d = fmaf(wh[m], s_ys[m * L + t], d);
            s_ah[t] = fsig(d);
        } else if (t >= 160 && t < 160 + W) {
            int l = t - 160;
            float d = 0.f;
            #pragma unroll
            for (int m = 0; m < MIP; m++) d = fmaf(ww[m], s_ys[m * L + H + l], d);
            s_aw[l] = fsig(d);
        }
        __syncthreads();
        const float4* buf = bufs + (j % 3) * 1600;
        const size_t  ob  = (size_t)(j * C + b) * 1600;
        const float4  aw4 = *(const float4*)(s_aw + 4 * q);
        #pragma unroll
        for (int i = 0; i < 5; i++) {
            int r = i * 16 + rg;
            float4 v  = buf[r * 20 + q];
            float  ah = s_ah[r];
            float4 rr;
            rr.x = v.x * (ah * aw4.x);
            rr.y = v.y * (ah * aw4.y);
            rr.z = v.z * (ah * aw4.z);
            rr.w = v.w * (ah * aw4.w);
            __stcs(o4 + ob + r * 20 + q, rr);
        }
    };

    for (int k = 0; k < NB; k++) {
        // 1. front-issue plane-k loads (in flight during do_C)
        const float* xp = x + (size_t)(k * C + b) * 6400;
        float4 v[5];
        #pragma unroll
        for (int i = 0; i < 5; i++)
            v[i] = ldg_nc4(xp + ((i * 16 + rg) * 20 + q) * 4);

        // 2. consume batch k-2 (overlaps with the loads above)
        if (k >= 2) do_C(k - 2);

        // 3. stage plane + reduce means + publish
        __syncthreads();
        float4* buf = bufs + (k % 3) * 1600;
        float4 cacc = make_float4(0.f, 0.f, 0.f, 0.f);
        #pragma unroll
        for (int i = 0; i < 5; i++) {
            int r = i * 16 + rg;
            buf[r * 20 + q] = v[i];
            cacc.x += v[i].x; cacc.y += v[i].y; cacc.z += v[i].z; cacc.w += v[i].w;
            s_row[r * 21 + q] = (v[i].x + v[i].y) + (v[i].z + v[i].w);
        }
        s_col[(4 * q + 0) * 17 + rg] = cacc.x;
        s_col[(4 * q + 1) * 17 + rg] = cacc.y;
        s_col[(4 * q + 2) * 17 + rg] = cacc.z;
        s_col[(4 * q + 3) * 17 + rg] = cacc.w;
        __syncthreads();

        float* gy = g_y + ((size_t)k * C + b) * L;
        if (t < H) {
            float s = 0.f;
            #pragma unroll
            for (int j2 = 0; j2 < 20; j2++) s += s_row[t * 21 + j2];
            gy[t] = s * inv80;                           // x_h
        } else if (t >= 160 && t < 160 + W) {
            int col = t - 160;
            float s = 0.f;
            #pragma unroll
            for (int g = 0; g < 16; g++) s += s_col[col * 17 + g];
            gy[H + col] = s * inv80;                     // x_w
        }
        __threadfence();
        __syncthreads();
        if (t == 0) atomicAdd(&g_cnt[k], 1);

        // 4. designated GEMM1 slice: blocks 16k..16k+15 each do 10 l-values
        if ((b >> 4) == k) {
            if (t == 0) { while (ld_acq(&g_cnt[k]) != GRID) __nanosleep(64); }
            __syncthreads();
            const int warp = t >> 5, lane = t & 31;
            const int l = (b & 15) * 10 + warp;          // 10 warps -> 10 l's
            const float* yb = g_y + (size_t)k * C * L;
            float ym[8];
            #pragma unroll
            for (int j2 = 0; j2 < 8; j2++)
                ym[j2] = ldcg(yb + (lane + 32 * j2) * L + l);
            float acc[MIP];
            #pragma unroll
            for (int m = 0; m < MIP; m++) acc[m] = 0.f;
            #pragma unroll
            for (int j2 = 0; j2 < 8; j2++) {
                int c = lane + 32 * j2;
                #pragma unroll
                for (int m = 0; m < MIP; m++)
                    acc[m] = fmaf(s_wfc[m * C + c], ym[j2], acc[m]);
            }
            #pragma unroll
            for (int off = 16; off > 0; off >>= 1) {
                #pragma unroll
                for (int m = 0; m < MIP; m++)
                    acc[m] += __shfl_xor_sync(0xffffffffu, acc[m], off);
            }
            if (lane < MIP) {
                float s  = acc[lane];
                float vv = s * s_bn[lane] + s_bn[MIP + lane];
                g_ysw[(size_t)k * MIP * L + lane * L + l] = vv * fsig(vv);
            }
            __threadfence();
            __syncthreads();
            if (t == 0) atomicAdd(&g_rdy[k], 1);
        }
    }
    do_C(NB - 2);
    do_C(NB - 1);
}

// ---------------------------------------------------------------------------
extern "C" void kernel_launch(void* const* d_in, const int* in_sizes, int n_in,
                              void* d_out, int out_size) {
    const float* x        = (const float*)d_in[0];
    const float* w_fc     = (const float*)d_in[1];
    const float* bn_gamma = (const float*)d_in[2];
    const float* bn_beta  = (const float*)d_in[3];
    const float* bn_mean  = (const float*)d_in[4];
    const float* bn_var   = (const float*)d_in[5];
    const float* w_h      = (const float*)d_in[6];
    const float* w_w      = (const float*)d_in[7];
    float* out = (float*)d_out;

    static int smem_set = 0;
    if (!smem_set) {
        cudaFuncSetAttribute(fused, cudaFuncAttributeMaxDynamicSharedMemorySize,
                             SM_FLOATS * sizeof(float));
        smem_set = 1;
    }

    init_state<<<1, 32>>>();
    fused<<<GRID, TPB, SM_FLOATS * sizeof(float)>>>(x, w_fc, bn_gamma, bn_beta,
                                                    bn_mean, bn_var, w_h, w_w, out);
}

// round 15
// speedup vs baseline: 1.9789x; 1.6967x over previous
#include <cuda_runtime.h>
#include <math.h>

#define NB  16
#define C   256
#define H   80
#define W   80
#define MIP 8
#define L   160            // H + W
#define BN_EPS 1e-5f

// Scratch (device globals: no allocations allowed)
__device__ float g_y [NB * C * L];   // [n][c][l]: l<80 row means (x_h), l>=80 col means (x_w)
__device__ float g_ah[NB * C * H];
__device__ float g_aw[NB * C * W];

__device__ __forceinline__ float fsig(float v) { return 1.f / (1.f + __expf(-v)); }

// ---------------------------------------------------------------------------
// k1 (R7-proven, 21.1us @ 5.16 TB/s): one block (320 thr) per plane.
// 20 col-groups x 16 row-groups; column partials in registers, small partials
// through padded smem.
// ---------------------------------------------------------------------------
__global__ __launch_bounds__(320) void k1_means(const float* __restrict__ x) {
    __shared__ float s_row[H][21];     // 21: gcd(21,32)=1
    __shared__ float s_col[W][17];     // 17: gcd(17,32)=1
    const int plane = blockIdx.x;
    const int t  = threadIdx.x;
    const int q  = t % 20;             // float4 column group
    const int rg = t / 20;             // row group 0..15
    const float4* __restrict__ xp = (const float4*)(x + (size_t)plane * (H * W));

    float4 cacc = make_float4(0.f, 0.f, 0.f, 0.f);
    #pragma unroll
    for (int i = 0; i < 5; i++) {
        int r = i * 16 + rg;
        float4 v = xp[r * 20 + q];
        cacc.x += v.x; cacc.y += v.y; cacc.z += v.z; cacc.w += v.w;
        s_row[r][q] = v.x + v.y + v.z + v.w;
    }
    s_col[4 * q + 0][rg] = cacc.x;
    s_col[4 * q + 1][rg] = cacc.y;
    s_col[4 * q + 2][rg] = cacc.z;
    s_col[4 * q + 3][rg] = cacc.w;
    __syncthreads();

    const float inv80 = 1.0f / 80.0f;
    if (t < H) {
        float s = 0.f;
        #pragma unroll
        for (int j = 0; j < 20; j++) s += s_row[t][j];
        g_y[(size_t)plane * L + t] = s * inv80;          // x_h (row mean)
    } else if (t >= 160 && t < 160 + W) {
        int col = t - 160;
        float s = 0.f;
        #pragma unroll
        for (int g = 0; g < 16; g++) s += s_col[col][g];
        g_y[(size_t)plane * L + H + col] = s * inv80;    // x_w (col mean)
    }
}

// ---------------------------------------------------------------------------
// k2 (R7-proven): grid (16, 2), block 320.
// GEMM1 split-K (MLP 8) + smem combine + BN + swish; GEMM2 register-hoisted.
// ---------------------------------------------------------------------------
__global__ __launch_bounds__(320) void k2_attn(const float* __restrict__ w_fc,
                                               const float* __restrict__ bn_gamma,
                                               const float* __restrict__ bn_beta,
                                               const float* __restrict__ bn_mean,
                                               const float* __restrict__ bn_var,
                                               const float* __restrict__ w_h,
                                               const float* __restrict__ w_w) {
    __shared__ float ys[MIP * L];        // swished bottleneck (5 KB)
    __shared__ float wfcT[C * MIP];      // w_fc transposed (8 KB)
    __shared__ float ps[2 * MIP * L];    // split-K partials (10 KB)
    const int n = blockIdx.x;
    const int t = threadIdx.x;

    if (t < C) {
        #pragma unroll
        for (int m = 0; m < MIP; m++) wfcT[t * MIP + m] = w_fc[m * C + t];
    }
    __syncthreads();

    const float* __restrict__ yb = g_y + (size_t)n * C * L;
    {
        const int l    = t % L;
        const int half = t / L;                          // 0 or 1
        const int c0   = half * (C / 2);
        float acc[MIP];
        #pragma unroll
        for (int m = 0; m < MIP; m++) acc[m] = 0.f;
        #pragma unroll 8
        for (int c = 0; c < C / 2; c++) {
            float v = yb[(c0 + c) * L + l];              // coalesced across threads
            const float4* wr = (const float4*)(wfcT + (c0 + c) * MIP);
            float4 a = wr[0], b = wr[1];
            acc[0] = fmaf(a.x, v, acc[0]); acc[1] = fmaf(a.y, v, acc[1]);
            acc[2] = fmaf(a.z, v, acc[2]); acc[3] = fmaf(a.w, v, acc[3]);
            acc[4] = fmaf(b.x, v, acc[4]); acc[5] = fmaf(b.y, v, acc[5]);
            acc[6] = fmaf(b.z, v, acc[6]); acc[7] = fmaf(b.w, v, acc[7]);
        }
        #pragma unroll
        for (int m = 0; m < MIP; m++) ps[half * MIP * L + m * L + l] = acc[m];
    }
    __syncthreads();

    if (t < L) {
        #pragma unroll
        for (int m = 0; m < MIP; m++) {
            float s  = ps[m * L + t] + ps[MIP * L + m * L + t];
            float iv = bn_gamma[m] * rsqrtf(bn_var[m] + BN_EPS);
            float vv = s * iv + (bn_beta[m] - bn_mean[m] * iv);
            ys[m * L + t] = vv * fsig(vv);
        }
    }
    __syncthreads();

    const int l  = t % 80;
    const int cg = t / 80;                               // 0..3
    const int c0 = (blockIdx.y * 4 + cg) * 32;
    float yh[MIP], yw[MIP];
    #pragma unroll
    for (int m = 0; m < MIP; m++) { yh[m] = ys[m * L + l]; yw[m] = ys[m * L + H + l]; }

    float* __restrict__ ahp = g_ah + (size_t)n * C * H;
    float* __restrict__ awp = g_aw + (size_t)n * C * W;
    #pragma unroll 4
    for (int c = c0; c < c0 + 32; c++) {
        const float4* wh4 = (const float4*)(w_h + c * MIP);
        const float4* ww4 = (const float4*)(w_w + c * MIP);
        float4 ha = wh4[0], hb = wh4[1];
        float4 wa = ww4[0], wb = ww4[1];
        float sh = 0.f, sw = 0.f;
        sh = fmaf(ha.x, yh[0], sh); sh = fmaf(ha.y, yh[1], sh);
        sh = fmaf(ha.z, yh[2], sh); sh = fmaf(ha.w, yh[3], sh);
        sh = fmaf(hb.x, yh[4], sh); sh = fmaf(hb.y, yh[5], sh);
        sh = fmaf(hb.z, yh[6], sh); sh = fmaf(hb.w, yh[7], sh);
        sw = fmaf(wa.x, yw[0], sw); sw = fmaf(wa.y, yw[1], sw);
        sw = fmaf(wa.z, yw[2], sw); sw = fmaf(wa.w, yw[3], sw);
        sw = fmaf(wb.x, yw[4], sw); sw = fmaf(wb.y, yw[5], sw);
        sw = fmaf(wb.z, yw[6], sw); sw = fmaf(wb.w, yw[7], sw);
        ahp[c * H + l] = fsig(sh);
        awp[c * W + l] = fsig(sw);
    }
}

// ---------------------------------------------------------------------------
// k3: EXACT k1 geometry (the shape measured at 5.16 TB/s): 4096 blocks x 320
// threads, one plane per block, 20 col-groups x 16 row-groups, 5 front-batched
// LDG.128 per thread, then 5 streaming STG.128.
// ---------------------------------------------------------------------------
__global__ __launch_bounds__(320) void k3_apply(const float* __restrict__ x,
                                                float* __restrict__ out) {
    __shared__ float  s_ah[H];
    __shared__ float4 s_aw4[20];
    const int plane = blockIdx.x;
    const int t  = threadIdx.x;
    const int q  = t % 20;
    const int rg = t / 20;

    if (t < H)            s_ah[t]      = g_ah[(size_t)plane * H + t];
    else if (t < H + 20)  s_aw4[t - H] = ((const float4*)g_aw)[(size_t)plane * 20 + (t - H)];
    __syncthreads();

    const float4* __restrict__ xp = (const float4*)x + (size_t)plane * 1600;
    float4* __restrict__ op = (float4*)out + (size_t)plane * 1600;

    float4 v[5];
    #pragma unroll
    for (int i = 0; i < 5; i++)                  // 5 LDG.128 in flight before any use
        v[i] = xp[(i * 16 + rg) * 20 + q];

    const float4 aw = s_aw4[q];
    #pragma unroll
    for (int i = 0; i < 5; i++) {
        int r = i * 16 + rg;
        float ah = s_ah[r];
        float4 rr;
        rr.x = v[i].x * (ah * aw.x);
        rr.y = v[i].y * (ah * aw.y);
        rr.z = v[i].z * (ah * aw.z);
        rr.w = v[i].w * (ah * aw.w);
        __stcs(op + r * 20 + q, rr);
    }
}

// ---------------------------------------------------------------------------
extern "C" void kernel_launch(void* const* d_in, const int* in_sizes, int n_in,
                              void* d_out, int out_size) {
    const float* x        = (const float*)d_in[0];
    const float* w_fc     = (const float*)d_in[1];
    const float* bn_gamma = (const float*)d_in[2];
    const float* bn_beta  = (const float*)d_in[3];
    const float* bn_mean  = (const float*)d_in[4];
    const float* bn_var   = (const float*)d_in[5];
    const float* w_h      = (const float*)d_in[6];
    const float* w_w      = (const float*)d_in[7];
    float* out = (float*)d_out;

    k1_means<<<NB * C, 320>>>(x);
    k2_attn<<<dim3(NB, 2), 320>>>(w_fc, bn_gamma, bn_beta, bn_mean, bn_var, w_h, w_w);
    k3_apply<<<NB * C, 320>>>(x, out);
}

// round 16
// speedup vs baseline: 2.1196x; 1.0711x over previous
#include <cuda_runtime.h>
#include <math.h>

#define NB  16
#define C   256
#define H   80
#define W   80
#define MIP 8
#define L   160            // H + W
#define BN_EPS 1e-5f

// Scratch (device globals: no allocations allowed)
__device__ float g_y [NB * C * L];   // [n][c][l]: l<80 row means (x_h), l>=80 col means (x_w)
__device__ float g_ah[NB * C * H];
__device__ float g_aw[NB * C * W];

__device__ __forceinline__ float fsig(float v) { return 1.f / (1.f + __expf(-v)); }

// Write-through store: push the out stream through L2 without retaining lines,
// so it does not evict the (fully resident) x planes that k3 still needs.
__device__ __forceinline__ void stwt4(float4* p, float4 v) {
    asm volatile("st.global.wt.v4.f32 [%0], {%1,%2,%3,%4};"
                 :: "l"(p), "f"(v.x), "f"(v.y), "f"(v.z), "f"(v.w) : "memory");
}

// ---------------------------------------------------------------------------
// k1 (R7-proven, ~21us @ 5.2 TB/s): one block (320 thr) per plane.
// 20 col-groups x 16 row-groups; column partials in registers, small partials
// through padded smem. Ascending plane order (k3 runs descending).
// ---------------------------------------------------------------------------
__global__ __launch_bounds__(320) void k1_means(const float* __restrict__ x) {
    __shared__ float s_row[H][21];     // 21: gcd(21,32)=1
    __shared__ float s_col[W][17];     // 17: gcd(17,32)=1
    const int plane = blockIdx.x;
    const int t  = threadIdx.x;
    const int q  = t % 20;             // float4 column group
    const int rg = t / 20;             // row group 0..15
    const float4* __restrict__ xp = (const float4*)(x + (size_t)plane * (H * W));

    float4 cacc = make_float4(0.f, 0.f, 0.f, 0.f);
    #pragma unroll
    for (int i = 0; i < 5; i++) {
        int r = i * 16 + rg;
        float4 v = xp[r * 20 + q];
        cacc.x += v.x; cacc.y += v.y; cacc.z += v.z; cacc.w += v.w;
        s_row[r][q] = v.x + v.y + v.z + v.w;
    }
    s_col[4 * q + 0][rg] = cacc.x;
    s_col[4 * q + 1][rg] = cacc.y;
    s_col[4 * q + 2][rg] = cacc.z;
    s_col[4 * q + 3][rg] = cacc.w;
    __syncthreads();

    const float inv80 = 1.0f / 80.0f;
    if (t < H) {
        float s = 0.f;
        #pragma unroll
        for (int j = 0; j < 20; j++) s += s_row[t][j];
        g_y[(size_t)plane * L + t] = s * inv80;          // x_h (row mean)
    } else if (t >= 160 && t < 160 + W) {
        int col = t - 160;
        float s = 0.f;
        #pragma unroll
        for (int g = 0; g < 16; g++) s += s_col[col][g];
        g_y[(size_t)plane * L + H + col] = s * inv80;    // x_w (col mean)
    }
}

// ---------------------------------------------------------------------------
// k2 (R7-proven): grid (16, 2), block 320.
// GEMM1 split-K (MLP 8) + smem combine + BN + swish; GEMM2 register-hoisted.
// ---------------------------------------------------------------------------
__global__ __launch_bounds__(320) void k2_attn(const float* __restrict__ w_fc,
                                               const float* __restrict__ bn_gamma,
                                               const float* __restrict__ bn_beta,
                                               const float* __restrict__ bn_mean,
                                               const float* __restrict__ bn_var,
                                               const float* __restrict__ w_h,
                                               const float* __restrict__ w_w) {
    __shared__ float ys[MIP * L];        // swished bottleneck (5 KB)
    __shared__ float wfcT[C * MIP];      // w_fc transposed (8 KB)
    __shared__ float ps[2 * MIP * L];    // split-K partials (10 KB)
    const int n = blockIdx.x;
    const int t = threadIdx.x;

    if (t < C) {
        #pragma unroll
        for (int m = 0; m < MIP; m++) wfcT[t * MIP + m] = w_fc[m * C + t];
    }
    __syncthreads();

    const float* __restrict__ yb = g_y + (size_t)n * C * L;
    {
        const int l    = t % L;
        const int half = t / L;                          // 0 or 1
        const int c0   = half * (C / 2);
        float acc[MIP];
        #pragma unroll
        for (int m = 0; m < MIP; m++) acc[m] = 0.f;
        #pragma unroll 8
        for (int c = 0; c < C / 2; c++) {
            float v = yb[(c0 + c) * L + l];              // coalesced across threads
            const float4* wr = (const float4*)(wfcT + (c0 + c) * MIP);
            float4 a = wr[0], b = wr[1];
            acc[0] = fmaf(a.x, v, acc[0]); acc[1] = fmaf(a.y, v, acc[1]);
            acc[2] = fmaf(a.z, v, acc[2]); acc[3] = fmaf(a.w, v, acc[3]);
            acc[4] = fmaf(b.x, v, acc[4]); acc[5] = fmaf(b.y, v, acc[5]);
            acc[6] = fmaf(b.z, v, acc[6]); acc[7] = fmaf(b.w, v, acc[7]);
        }
        #pragma unroll
        for (int m = 0; m < MIP; m++) ps[half * MIP * L + m * L + l] = acc[m];
    }
    __syncthreads();

    if (t < L) {
        #pragma unroll
        for (int m = 0; m < MIP; m++) {
            float s  = ps[m * L + t] + ps[MIP * L + m * L + t];
            float iv = bn_gamma[m] * rsqrtf(bn_var[m] + BN_EPS);
            float vv = s * iv + (bn_beta[m] - bn_mean[m] * iv);
            ys[m * L + t] = vv * fsig(vv);
        }
    }
    __syncthreads();

    const int l  = t % 80;
    const int cg = t / 80;                               // 0..3
    const int c0 = (blockIdx.y * 4 + cg) * 32;
    float yh[MIP], yw[MIP];
    #pragma unroll
    for (int m = 0; m < MIP; m++) { yh[m] = ys[m * L + l]; yw[m] = ys[m * L + H + l]; }

    float* __restrict__ ahp = g_ah + (size_t)n * C * H;
    float* __restrict__ awp = g_aw + (size_t)n * C * W;
    #pragma unroll 4
    for (int c = c0; c < c0 + 32; c++) {
        const float4* wh4 = (const float4*)(w_h + c * MIP);
        const float4* ww4 = (const float4*)(w_w + c * MIP);
        float4 ha = wh4[0], hb = wh4[1];
        float4 wa = ww4[0], wb = ww4[1];
        float sh = 0.f, sw = 0.f;
        sh = fmaf(ha.x, yh[0], sh); sh = fmaf(ha.y, yh[1], sh);
        sh = fmaf(ha.z, yh[2], sh); sh = fmaf(ha.w, yh[3], sh);
        sh = fmaf(hb.x, yh[4], sh); sh = fmaf(hb.y, yh[5], sh);
        sh = fmaf(hb.z, yh[6], sh); sh = fmaf(hb.w, yh[7], sh);
        sw = fmaf(wa.x, yw[0], sw); sw = fmaf(wa.y, yw[1], sw);
        sw = fmaf(wa.z, yw[2], sw); sw = fmaf(wa.w, yw[3], sw);
        sw = fmaf(wb.x, yw[4], sw); sw = fmaf(wb.y, yw[5], sw);
        sw = fmaf(wb.z, yw[6], sw); sw = fmaf(wb.w, yw[7], sw);
        ahp[c * H + l] = fsig(sh);
        awp[c * W + l] = fsig(sw);
    }
}

// ---------------------------------------------------------------------------
// k3 (R7-proven shape): 1024 blocks x 256 thr, 4 consecutive planes per block,
// DESCENDING plane order (consume most-recently-cached x first). a-maps staged
// in smem; 5-wide front-batched LDG.128; out written WRITE-THROUGH so the
// write stream does not evict x from L2.
// ---------------------------------------------------------------------------
__global__ __launch_bounds__(256) void k3_apply(const float* __restrict__ x,
                                                float* __restrict__ out) {
    __shared__ float  s_ah[4 * H];       // 4 planes of a_h (320 floats)
    __shared__ float4 s_aw[4 * 20];      // 4 planes of a_w as float4 (80 entries)
    const int pb  = 1023 - blockIdx.x;   // 4-plane group, descending
    const int tid = threadIdx.x;
    const size_t base = (size_t)pb * 6400;   // float4 base

    for (int i = tid; i < 4 * H; i += 256)
        s_ah[i] = g_ah[pb * 4 * H + i];
    if (tid < 4 * 20)
        s_aw[tid] = ((const float4*)g_aw)[pb * 4 * 20 + tid];
    __syncthreads();

    const float4* __restrict__ x4 = (const float4*)x;
    float4* __restrict__ o4 = (float4*)out;

    #pragma unroll
    for (int batch = 0; batch < 5; batch++) {
        float4 xv[5];
        int    idx[5];
        #pragma unroll
        for (int jj = 0; jj < 5; jj++) {
            idx[jj] = (batch * 5 + jj) * 256 + tid;      // [0, 6400)
            xv[jj]  = x4[base + idx[jj]];
        }
        #pragma unroll
        for (int jj = 0; jj < 5; jj++) {
            const int v   = idx[jj];
            const int lp  = v / 1600;                    // local plane 0..3
            const int rem = v - lp * 1600;
            const int hh  = rem / 20;
            const int q   = rem - hh * 20;
            const float  ah  = s_ah[lp * H + hh];
            const float4 aw4 = s_aw[lp * 20 + q];
            float4 r;
            r.x = xv[jj].x * (ah * aw4.x);
            r.y = xv[jj].y * (ah * aw4.y);
            r.z = xv[jj].z * (ah * aw4.z);
            r.w = xv[jj].w * (ah * aw4.w);
            stwt4(o4 + base + v, r);
        }
    }
}

// ---------------------------------------------------------------------------
extern "C" void kernel_launch(void* const* d_in, const int* in_sizes, int n_in,
                              void* d_out, int out_size) {
    const float* x        = (const float*)d_in[0];
    const float* w_fc     = (const float*)d_in[1];
    const float* bn_gamma = (const float*)d_in[2];
    const float* bn_beta  = (const float*)d_in[3];
    const float* bn_mean  = (const float*)d_in[4];
    const float* bn_var   = (const float*)d_in[5];
    const float* w_h      = (const float*)d_in[6];
    const float* w_w      = (const float*)d_in[7];
    float* out = (float*)d_out;

    k1_means<<<NB * C, 320>>>(x);
    k2_attn<<<dim3(NB, 2), 320>>>(w_fc, bn_gamma, bn_beta, bn_mean, bn_var, w_h, w_w);
    k3_apply<<<1024, 256>>>(x, out);
}